// round 7
// baseline (speedup 1.0000x reference)
#include <cuda_runtime.h>
#include <cuda_fp16.h>
#include <math.h>

// ---------------------------------------------------------------------------
// GatingNeuralAdaptiveBias — 1D lookup tables (fp16) + fast table build.
//   tab_ch[x] = [ e_ch(x)+eb_ch (64) | g_ch(x) (64) ]   (fp16, 256B/entry)
//   w0 = sigmoid((silu(g0+g1) . wg2d + bg2d) * itemp)
//   out = LN(w0*e0+w1*e1) . (ln_gamma*Wo) + sbw         (LN folded)
// Main: 4 lanes/pixel, 16 dims/lane, 16x16B table loads, quad shuffles.
// ---------------------------------------------------------------------------

typedef unsigned int uint;
typedef unsigned short ushort;

#define PI_F 3.14159265358979323846f
#define N0 2048
#define N1 8192

__device__ __align__(16) ushort g_tab0h[(N0 + 64) * 128];  // fp16 [e|g]
__device__ __align__(16) ushort g_tab1h[(N1 + 64) * 128];
__device__ __align__(16) float  g_wc[2 * 64 * 64];

#define GP_C1   0     // 64 : ln_gamma*Wo
#define GP_WG2D 64    // 64 : Wg2[:,0]-Wg2[:,1]
#define GP_BGC  128   // 64 : folded gate bias
#define GP_EB   192   // 128: b2*gamma+beta per ch
#define GP_SC   320   // 8  : scl0, scl1, itemp, sbw, bg2d, c1s
#define GP_TOT  328
__device__ __align__(16) float g_pre[GP_TOT];

__device__ __forceinline__ float silu_f(float v) {
    return __fdividef(v, 1.0f + __expf(-v));
}

// ========================= consts kernel ===================================
__global__ void k_consts(const float* __restrict__ log_scale,
                         const float* __restrict__ b2,
                         const float* __restrict__ fg,  const float* __restrict__ fb,
                         const float* __restrict__ Wg1, const float* __restrict__ bg1,
                         const float* __restrict__ Wg2, const float* __restrict__ bg2,
                         const float* __restrict__ temp,
                         const float* __restrict__ lng, const float* __restrict__ lnb,
                         const float* __restrict__ Wo,  const float* __restrict__ bo)
{
    const int tid = threadIdx.x;   // 128
    if (tid < 64) {
        g_pre[GP_C1 + tid]   = lng[tid] * Wo[tid];
        g_pre[GP_WG2D + tid] = Wg2[tid * 2] - Wg2[tid * 2 + 1];
        float a = bg1[tid];
        for (int k = 0; k < 64; k++) {
            a = fmaf(b2[k] * fg[k]      + fb[k],      Wg1[k * 64 + tid],        a);
            a = fmaf(b2[k] * fg[64 + k] + fb[64 + k], Wg1[(64 + k) * 64 + tid], a);
        }
        g_pre[GP_BGC + tid] = a;
    }
    if (tid < 128) {
        const int c = tid >> 6, k = tid & 63;
        g_pre[GP_EB + tid] = b2[k] * fg[c * 64 + k] + fb[c * 64 + k];
    }
    if (tid == 0) {
        g_pre[GP_SC + 0] = expf(log_scale[0]);
        g_pre[GP_SC + 1] = expf(log_scale[1]);
        g_pre[GP_SC + 2] = expf(-temp[0]);
        float s = bo[0], cs = 0.0f;
        for (int k = 0; k < 64; k++) { s += lnb[k] * Wo[k]; cs += lng[k] * Wo[k]; }
        g_pre[GP_SC + 3] = s;
        g_pre[GP_SC + 4] = bg2[0] - bg2[1];
        g_pre[GP_SC + 5] = cs;
        g_pre[GP_SC + 6] = 0.0f;
        g_pre[GP_SC + 7] = 0.0f;
    }
}

// ========================= Wc fold kernel ==================================
__global__ void k_wc(const float* __restrict__ W2,
                     const float* __restrict__ fg,
                     const float* __restrict__ Wg1)
{
    const int bid = blockIdx.x;    // 128: ch*64 + j
    const int ch  = bid >> 6;
    const int j   = bid & 63;
    const int o   = threadIdx.x;   // 64
    float acc = 0.0f;
    for (int m = 0; m < 64; m++)
        acc = fmaf(W2[j * 64 + m] * fg[ch * 64 + m], Wg1[(ch * 64 + m) * 64 + o], acc);
    g_wc[ch * 4096 + j * 64 + o] = acc;
}

// ========================= table build (smem-staged) =======================
// 256 threads = 4 nodes x 64 dims; 64 nodes per block; weights staged once.
#define CH0_BLOCKS 33          // ceil(2049/64)
#define CH1_BLOCKS 129         // ceil(8193/64)
__global__ void __launch_bounds__(256)
k_tables(const float* __restrict__ W1, const float* __restrict__ b1,
         const float* __restrict__ W2, const float* __restrict__ fg)
{
    __shared__ float sW2g[4096];
    __shared__ float sWc[4096];
    __shared__ float sW1[576];
    __shared__ float sb1[64];
    __shared__ float sh[4 * 64];

    const int tid = threadIdx.x;
    const int ch   = (blockIdx.x < CH0_BLOCKS) ? 0 : 1;
    const int base = ch ? (blockIdx.x - CH0_BLOCKS) * 64 : blockIdx.x * 64;

    for (int t = tid; t < 4096; t += 256) {
        sW2g[t] = W2[t] * fg[ch * 64 + (t & 63)];
        sWc[t]  = g_wc[ch * 4096 + t];
    }
    for (int t = tid; t < 576; t += 256) sW1[t] = W1[t];
    if (tid < 64) sb1[tid] = b1[tid];
    __syncthreads();

    const float sc   = g_pre[GP_SC + ch];
    const int   grp  = tid >> 6;
    const int   dim  = tid & 63;
    const int   ncap = ch ? N1 : N0;
    const float eb   = g_pre[GP_EB + ch * 64 + dim];
    const float gb   = (ch == 0) ? g_pre[GP_BGC + dim] : 0.0f;
    ushort* tab = ch ? g_tab1h : g_tab0h;

    #pragma unroll 1
    for (int round = 0; round < 16; round++) {
        const int ent = base + round * 4 + grp;
        const float x = ch ? (-PI_F + (float)ent * (2.0f * PI_F / N1))
                           : ((float)ent * (1.0f / N0));
        float ft[9];
        ft[0] = x * sc;
        #pragma unroll
        for (int q = 0; q < 4; q++) {
            float s, c;
            sincosf(x * (float)(1 << q), &s, &c);
            ft[1 + 2 * q] = s * sc;
            ft[2 + 2 * q] = c * sc;
        }
        float z = sb1[dim];
        #pragma unroll
        for (int f = 0; f < 9; f++) z = fmaf(ft[f], sW1[f * 64 + dim], z);
        sh[grp * 64 + dim] = z / (1.0f + expf(-z));
        __syncthreads();

        float e = eb, g = gb;
        #pragma unroll 4
        for (int j = 0; j < 64; j++) {
            const float hj = sh[grp * 64 + j];
            e = fmaf(hj, sW2g[j * 64 + dim], e);
            g = fmaf(hj, sWc[j * 64 + dim],  g);
        }
        if (ent <= ncap) {
            tab[ent * 128 + dim]      = __half_as_ushort(__float2half_rn(e));
            tab[ent * 128 + 64 + dim] = __half_as_ushort(__float2half_rn(g));
        }
        __syncthreads();
    }
}

// ========================= main kernel =====================================
// convert 8 fp16 (uint4) from two nodes + lerp -> 8 floats
__device__ __forceinline__ void lerp8(uint4 A, uint4 B, float f, float* o) {
    const __half2* a = reinterpret_cast<const __half2*>(&A);
    const __half2* b = reinterpret_cast<const __half2*>(&B);
    #pragma unroll
    for (int i = 0; i < 4; i++) {
        const float2 fa = __half22float2(a[i]);
        const float2 fb = __half22float2(b[i]);
        o[2 * i]     = fmaf(f, fb.x - fa.x, fa.x);
        o[2 * i + 1] = fmaf(f, fb.y - fa.y, fa.y);
    }
}

__global__ void __launch_bounds__(256)
gnab_main(const float* __restrict__ coords,
          const float* __restrict__ cost,
          float* __restrict__ out)
{
    __shared__ __align__(16) float s_c1[64];
    __shared__ __align__(16) float s_wg2d[64];
    __shared__ float s_sc[8];

    const int tid = threadIdx.x;
    if (tid < 64) {
        s_c1[tid]   = g_pre[GP_C1 + tid];
        s_wg2d[tid] = g_pre[GP_WG2D + tid];
    }
    if (tid < 8) s_sc[tid] = g_pre[GP_SC + tid];
    __syncthreads();

    const int px = tid >> 2;       // 0..63
    const int lq = tid & 3;

    const int bid = blockIdx.x;    // 8192 = 2048 rows * 4 segments
    const int row = bid >> 2;
    const int seg = bid & 3;
    const int b = row >> 8;
    const int i = row & 255;
    const int j = seg * 64 + px;
    const int pixel = row * 256 + j;

    const float x0 = __ldg(&cost[pixel]);
    const float dx = __ldg(&coords[(b * 256 + i) * 2 + 0]) - __ldg(&coords[(b * 256 + j) * 2 + 0]);
    const float dy = __ldg(&coords[(b * 256 + i) * 2 + 1]) - __ldg(&coords[(b * 256 + j) * 2 + 1]);
    const float x1 = atan2f(dy, dx);

    float u0 = x0 * (float)N0;
    int i0 = (int)u0;
    i0 = (i0 < 0) ? 0 : ((i0 > N0 - 1) ? N0 - 1 : i0);
    const float f0 = u0 - (float)i0;

    float u1 = (x1 + PI_F) * ((float)N1 / (2.0f * PI_F));
    int i1 = (int)u1;
    i1 = (i1 < 0) ? 0 : ((i1 > N1 - 1) ? N1 - 1 : i1);
    const float f1 = u1 - (float)i1;

    const uint4* t0 = reinterpret_cast<const uint4*>(g_tab0h);
    const uint4* t1 = reinterpret_cast<const uint4*>(g_tab1h);
    // entry = 16 uint4: e chunks [0..8), g chunks [8..16); lane owns 2 of each
    const int a0 = i0 * 16 + lq * 2, b0 = a0 + 16;
    const int a1 = i1 * 16 + lq * 2, b1i = a1 + 16;

    float le0[16], le1[16], g0v[16], g1v[16];
    #pragma unroll
    for (int c = 0; c < 2; c++) {
        lerp8(__ldg(&t0[a0 + c]),     __ldg(&t0[b0 + c]),      f0, &le0[c * 8]);
        lerp8(__ldg(&t1[a1 + c]),     __ldg(&t1[b1i + c]),     f1, &le1[c * 8]);
        lerp8(__ldg(&t0[a0 + 8 + c]), __ldg(&t0[b0 + 8 + c]),  f0, &g0v[c * 8]);
        lerp8(__ldg(&t1[a1 + 8 + c]), __ldg(&t1[b1i + 8 + c]), f1, &g1v[c * 8]);
    }

    // gate
    float gacc = 0.0f;
    #pragma unroll
    for (int t = 0; t < 16; t++)
        gacc = fmaf(silu_f(g0v[t] + g1v[t]), s_wg2d[lq * 16 + t], gacc);
    gacc += __shfl_xor_sync(0xFFFFFFFFu, gacc, 1);
    gacc += __shfl_xor_sync(0xFFFFFFFFu, gacc, 2);
    const float ldelta = gacc + s_sc[4];
    const float w0 = __fdividef(1.0f, 1.0f + __expf(-ldelta * s_sc[2]));
    const float w1 = 1.0f - w0;

    // fused + LN reductions
    float S = 0.0f, Q = 0.0f, D = 0.0f;
    #pragma unroll
    for (int t = 0; t < 16; t++) {
        const float f = fmaf(w0, le0[t], w1 * le1[t]);
        S += f;
        Q = fmaf(f, f, Q);
        D = fmaf(f, s_c1[lq * 16 + t], D);
    }
    S += __shfl_xor_sync(0xFFFFFFFFu, S, 1);
    S += __shfl_xor_sync(0xFFFFFFFFu, S, 2);
    Q += __shfl_xor_sync(0xFFFFFFFFu, Q, 1);
    Q += __shfl_xor_sync(0xFFFFFFFFu, Q, 2);
    D += __shfl_xor_sync(0xFFFFFFFFu, D, 1);
    D += __shfl_xor_sync(0xFFFFFFFFu, D, 2);

    if (lq == 0) {
        const float mu   = S * (1.0f / 64.0f);
        const float var  = Q * (1.0f / 64.0f) - mu * mu;
        const float rstd = rsqrtf(var + 1e-5f);
        const float dot  = D - mu * s_sc[5];
        out[pixel] = fmaf(dot, rstd, s_sc[3]);
    }
}

// ============================ launch =======================================
extern "C" void kernel_launch(void* const* d_in, const int* in_sizes, int n_in,
                              void* d_out, int out_size)
{
    const float* coords = (const float*)d_in[0];
    const float* cost   = (const float*)d_in[1];
    const float* lsc    = (const float*)d_in[2];
    const float* W1     = (const float*)d_in[3];
    const float* b1     = (const float*)d_in[4];
    const float* W2     = (const float*)d_in[5];
    const float* b2     = (const float*)d_in[6];
    const float* fg     = (const float*)d_in[7];
    const float* fb     = (const float*)d_in[8];
    const float* Wg1    = (const float*)d_in[9];
    const float* bg1    = (const float*)d_in[10];
    const float* Wg2    = (const float*)d_in[11];
    const float* bg2    = (const float*)d_in[12];
    const float* temp   = (const float*)d_in[13];
    const float* lng    = (const float*)d_in[14];
    const float* lnb    = (const float*)d_in[15];
    const float* Wo     = (const float*)d_in[16];
    const float* bo     = (const float*)d_in[17];
    float* out          = (float*)d_out;

    k_consts<<<1, 128>>>(lsc, b2, fg, fb, Wg1, bg1, Wg2, bg2,
                         temp, lng, lnb, Wo, bo);
    k_wc<<<128, 64>>>(W2, fg, Wg1);
    k_tables<<<CH0_BLOCKS + CH1_BLOCKS, 256>>>(W1, b1, W2, fg);
    gnab_main<<<8192, 256>>>(coords, cost, out);
}

// round 8
// speedup vs baseline: 1.1336x; 1.1336x over previous
#include <cuda_runtime.h>
#include <cuda_fp16.h>
#include <math.h>

// ---------------------------------------------------------------------------
// GatingNeuralAdaptiveBias — fp16 1D lookup tables, oct-per-pixel main kernel.
//   tab_ch[x] = [ e_ch(x)+eb_ch (64) | g_ch(x) (64) ]  fp16, 256B/entry
//   gate: w0 = sigmoid((silu(g0+g1).wg2d + bg2d) * itemp)
//   out  = LN(w0*e0+w1*e1) . (ln_gamma*Wo) + sbw        (LN folded)
// Setup = ONE kernel (g = e_raw @ Wg1 fold; consts from block 0).
// Main: 8 lanes/pixel; every 128B table half = one coalesced LDG.128.
// ---------------------------------------------------------------------------

typedef unsigned int uint;
typedef unsigned short ushort;

#define PI_F 3.14159265358979323846f
#define N0 2048
#define N1 8192

__device__ __align__(256) ushort g_tab0h[(N0 + 64) * 128];  // fp16 [e|g]
__device__ __align__(256) ushort g_tab1h[(N1 + 64) * 128];

#define GP_C1   0     // 64 : ln_gamma*Wo
#define GP_WG2D 64    // 64 : Wg2[:,0]-Wg2[:,1]
#define GP_SC   128   // 4  : itemp, sbw, bg2d, c1s
#define GP_TOT  132
__device__ __align__(16) float g_pre[GP_TOT];

__device__ __forceinline__ float silu_f(float v) {
    return __fdividef(v, 1.0f + __expf(-v));
}

// =================== single setup kernel: tables + consts ==================
#define CH0_BLOCKS 33          // ceil(2049/64)
#define CH1_BLOCKS 129         // ceil(8193/64)
__global__ void __launch_bounds__(256)
k_tables(const float* __restrict__ log_scale,
         const float* __restrict__ W1,  const float* __restrict__ b1,
         const float* __restrict__ W2,  const float* __restrict__ b2,
         const float* __restrict__ fg,  const float* __restrict__ fb,
         const float* __restrict__ Wg1, const float* __restrict__ bg1,
         const float* __restrict__ Wg2, const float* __restrict__ bg2,
         const float* __restrict__ temp,
         const float* __restrict__ lng, const float* __restrict__ lnb,
         const float* __restrict__ Wo,  const float* __restrict__ bo)
{
    __shared__ float sW2g[4096];    // W2 * gamma_ch (col-scaled)
    __shared__ float sWg1[4096];    // Wg1 half for ch
    __shared__ float sW1[576];
    __shared__ float sb1[64];
    __shared__ float sh[4 * 64];
    __shared__ float se[4 * 64];

    const int tid  = threadIdx.x;
    const int ch   = (blockIdx.x < CH0_BLOCKS) ? 0 : 1;
    const int base = ch ? (blockIdx.x - CH0_BLOCKS) * 64 : blockIdx.x * 64;

    // block 0 also publishes main-kernel constants
    if (blockIdx.x == 0) {
        if (tid < 64) {
            g_pre[GP_C1 + tid]   = lng[tid] * Wo[tid];
            g_pre[GP_WG2D + tid] = Wg2[tid * 2] - Wg2[tid * 2 + 1];
        }
        if (tid == 128) {
            float s = bo[0], cs = 0.0f;
            for (int k = 0; k < 64; k++) { s += lnb[k] * Wo[k]; cs += lng[k] * Wo[k]; }
            g_pre[GP_SC + 0] = expf(-temp[0]);
            g_pre[GP_SC + 1] = s;
            g_pre[GP_SC + 2] = bg2[0] - bg2[1];
            g_pre[GP_SC + 3] = cs;
        }
    }

    for (int t = tid; t < 4096; t += 256) {
        sW2g[t] = W2[t] * fg[ch * 64 + (t & 63)];
        sWg1[t] = Wg1[ch * 4096 + t];
    }
    for (int t = tid; t < 576; t += 256) sW1[t] = W1[t];
    if (tid < 64) sb1[tid] = b1[tid];
    __syncthreads();

    const int   grp  = tid >> 6;
    const int   dim  = tid & 63;
    const int   ncap = ch ? N1 : N0;
    const float sc   = expf(log_scale[ch]);
    const float eb   = b2[dim] * fg[ch * 64 + dim] + fb[ch * 64 + dim];
    float gb = 0.0f;
    if (ch == 0) {                 // folded gate bias (only added once)
        gb = bg1[dim];
        for (int k = 0; k < 64; k++) {
            gb = fmaf(b2[k] * fg[k]      + fb[k],      Wg1[k * 64 + dim],        gb);
            gb = fmaf(b2[k] * fg[64 + k] + fb[64 + k], Wg1[(64 + k) * 64 + dim], gb);
        }
    }
    ushort* tab = ch ? g_tab1h : g_tab0h;

    #pragma unroll 1
    for (int round = 0; round < 16; round++) {
        const int ent = base + round * 4 + grp;
        const float x = ch ? (-PI_F + (float)ent * (2.0f * PI_F / N1))
                           : ((float)ent * (1.0f / N0));
        float ft[9];
        ft[0] = x * sc;
        #pragma unroll
        for (int q = 0; q < 4; q++) {
            float s, c;
            sincosf(x * (float)(1 << q), &s, &c);
            ft[1 + 2 * q] = s * sc;
            ft[2 + 2 * q] = c * sc;
        }
        float z = sb1[dim];
        #pragma unroll
        for (int f = 0; f < 9; f++) z = fmaf(ft[f], sW1[f * 64 + dim], z);
        sh[grp * 64 + dim] = z / (1.0f + expf(-z));
        __syncthreads();

        float e = 0.0f;
        #pragma unroll 4
        for (int j = 0; j < 64; j++)
            e = fmaf(sh[grp * 64 + j], sW2g[j * 64 + dim], e);
        se[grp * 64 + dim] = e;
        if (ent <= ncap)
            tab[ent * 128 + dim] = __half_as_ushort(__float2half_rn(e + eb));
        __syncthreads();

        float g = gb;
        #pragma unroll 4
        for (int k = 0; k < 64; k++)
            g = fmaf(se[grp * 64 + k], sWg1[k * 64 + dim], g);
        if (ent <= ncap)
            tab[ent * 128 + 64 + dim] = __half_as_ushort(__float2half_rn(g));
        __syncthreads();
    }
}

// ========================= main kernel =====================================
__device__ __forceinline__ void lerp8(uint4 A, uint4 B, float f, float* o) {
    const __half2* a = reinterpret_cast<const __half2*>(&A);
    const __half2* b = reinterpret_cast<const __half2*>(&B);
    #pragma unroll
    for (int i = 0; i < 4; i++) {
        const float2 fa = __half22float2(a[i]);
        const float2 fb = __half22float2(b[i]);
        o[2 * i]     = fmaf(f, fb.x - fa.x, fa.x);
        o[2 * i + 1] = fmaf(f, fb.y - fa.y, fa.y);
    }
}

__global__ void __launch_bounds__(256)
gnab_main(const float* __restrict__ coords,
          const float* __restrict__ cost,
          float* __restrict__ out)
{
    __shared__ __align__(16) float s_c1[64];
    __shared__ __align__(16) float s_wg2d[64];
    __shared__ float s_sc[4];

    const int tid = threadIdx.x;
    if (tid < 64) {
        s_c1[tid]   = g_pre[GP_C1 + tid];
        s_wg2d[tid] = g_pre[GP_WG2D + tid];
    }
    if (tid < 4) s_sc[tid] = g_pre[GP_SC + tid];
    __syncthreads();

    const int lo  = tid & 7;          // lane in oct: owns dims [lo*8, lo*8+8)
    const int px  = tid >> 3;         // 0..31 pixel within block

    const int bid = blockIdx.x;       // 16384 = 2048 rows x 8 segments
    const int row = bid >> 3;
    const int seg = bid & 7;
    const int b = row >> 8;
    const int i = row & 255;
    const int j = seg * 32 + px;
    const int pixel = row * 256 + j;

    const float x0 = __ldg(&cost[pixel]);
    const float dx = __ldg(&coords[(b * 256 + i) * 2 + 0]) - __ldg(&coords[(b * 256 + j) * 2 + 0]);
    const float dy = __ldg(&coords[(b * 256 + i) * 2 + 1]) - __ldg(&coords[(b * 256 + j) * 2 + 1]);
    const float x1 = atan2f(dy, dx);

    float u0 = x0 * (float)N0;
    int i0 = (int)u0;
    i0 = (i0 < 0) ? 0 : ((i0 > N0 - 1) ? N0 - 1 : i0);
    const float f0 = u0 - (float)i0;

    float u1 = (x1 + PI_F) * ((float)N1 / (2.0f * PI_F));
    int i1 = (int)u1;
    i1 = (i1 < 0) ? 0 : ((i1 > N1 - 1) ? N1 - 1 : i1);
    const float f1 = u1 - (float)i1;

    const uint4* t0 = reinterpret_cast<const uint4*>(g_tab0h);
    const uint4* t1 = reinterpret_cast<const uint4*>(g_tab1h);
    // entry = 16 uint4: e in [0..8), g in [8..16); lane lo owns one uint4 each
    const int e0a = i0 * 16 + lo, e0b = e0a + 16;
    const int e1a = i1 * 16 + lo, e1b = e1a + 16;

    // issue all 8 independent 16B loads up front (MLP=8)
    const uint4 Ea0 = __ldg(&t0[e0a]);
    const uint4 Eb0 = __ldg(&t0[e0b]);
    const uint4 Ga0 = __ldg(&t0[e0a + 8]);
    const uint4 Gb0 = __ldg(&t0[e0b + 8]);
    const uint4 Ea1 = __ldg(&t1[e1a]);
    const uint4 Eb1 = __ldg(&t1[e1b]);
    const uint4 Ga1 = __ldg(&t1[e1a + 8]);
    const uint4 Gb1 = __ldg(&t1[e1b + 8]);

    float g0v[8], g1v[8], le0[8], le1[8];
    lerp8(Ga0, Gb0, f0, g0v);
    lerp8(Ga1, Gb1, f1, g1v);
    lerp8(Ea0, Eb0, f0, le0);
    lerp8(Ea1, Eb1, f1, le1);

    // gate
    float gacc = 0.0f;
    #pragma unroll
    for (int t = 0; t < 8; t++)
        gacc = fmaf(silu_f(g0v[t] + g1v[t]), s_wg2d[lo * 8 + t], gacc);
    gacc += __shfl_xor_sync(0xFFFFFFFFu, gacc, 1);
    gacc += __shfl_xor_sync(0xFFFFFFFFu, gacc, 2);
    gacc += __shfl_xor_sync(0xFFFFFFFFu, gacc, 4);
    const float w0 = __fdividef(1.0f, 1.0f + __expf(-(gacc + s_sc[2]) * s_sc[0]));
    const float w1 = 1.0f - w0;

    // fused + LN reductions
    float S = 0.0f, Q = 0.0f, D = 0.0f;
    #pragma unroll
    for (int t = 0; t < 8; t++) {
        const float f = fmaf(w0, le0[t], w1 * le1[t]);
        S += f;
        Q = fmaf(f, f, Q);
        D = fmaf(f, s_c1[lo * 8 + t], D);
    }
    S += __shfl_xor_sync(0xFFFFFFFFu, S, 1);
    S += __shfl_xor_sync(0xFFFFFFFFu, S, 2);
    S += __shfl_xor_sync(0xFFFFFFFFu, S, 4);
    Q += __shfl_xor_sync(0xFFFFFFFFu, Q, 1);
    Q += __shfl_xor_sync(0xFFFFFFFFu, Q, 2);
    Q += __shfl_xor_sync(0xFFFFFFFFu, Q, 4);
    D += __shfl_xor_sync(0xFFFFFFFFu, D, 1);
    D += __shfl_xor_sync(0xFFFFFFFFu, D, 2);
    D += __shfl_xor_sync(0xFFFFFFFFu, D, 4);

    if (lo == 0) {
        const float mu   = S * (1.0f / 64.0f);
        const float var  = Q * (1.0f / 64.0f) - mu * mu;
        const float rstd = rsqrtf(var + 1e-5f);
        const float dot  = D - mu * s_sc[3];
        out[pixel] = fmaf(dot, rstd, s_sc[1]);
    }
}

// ============================ launch =======================================
extern "C" void kernel_launch(void* const* d_in, const int* in_sizes, int n_in,
                              void* d_out, int out_size)
{
    const float* coords = (const float*)d_in[0];
    const float* cost   = (const float*)d_in[1];
    const float* lsc    = (const float*)d_in[2];
    const float* W1     = (const float*)d_in[3];
    const float* b1     = (const float*)d_in[4];
    const float* W2     = (const float*)d_in[5];
    const float* b2     = (const float*)d_in[6];
    const float* fg     = (const float*)d_in[7];
    const float* fb     = (const float*)d_in[8];
    const float* Wg1    = (const float*)d_in[9];
    const float* bg1    = (const float*)d_in[10];
    const float* Wg2    = (const float*)d_in[11];
    const float* bg2    = (const float*)d_in[12];
    const float* temp   = (const float*)d_in[13];
    const float* lng    = (const float*)d_in[14];
    const float* lnb    = (const float*)d_in[15];
    const float* Wo     = (const float*)d_in[16];
    const float* bo     = (const float*)d_in[17];
    float* out          = (float*)d_out;

    k_tables<<<CH0_BLOCKS + CH1_BLOCKS, 256>>>(
        lsc, W1, b1, W2, b2, fg, fb, Wg1, bg1, Wg2, bg2,
        temp, lng, lnb, Wo, bo);
    gnab_main<<<16384, 256>>>(coords, cost, out);
}